// round 2
// baseline (speedup 1.0000x reference)
#include <cuda_runtime.h>
#include <math.h>

#define NNODES 50000
#define NEDGES 800000
#define NGRAPHS 64
#define NLOCS 50

// ---------------- device scratch (globals: no allocation allowed) ----------------
__device__ float g_h[(size_t)NNODES * 144];    // GEMM output (features + es + ed), stride 144 (L0/L1) or 132 (L2)
__device__ float g_act[(size_t)NNODES * 132];  // gather output / next GEMM input
__device__ float g_Wp0[8 * 144];
__device__ float g_Wp1[132 * 144];
__device__ float g_Wp2[132 * 132];
__device__ int g_deg[NNODES];
__device__ int g_cur[NNODES];
__device__ int g_rowptr[NNODES + 1];
__device__ int g_col[NEDGES];
__device__ float g_pool[NGRAPHS * 128];
__device__ int g_cnt[NGRAPHS];

__device__ __forceinline__ float leakyf(float v) { return v > 0.f ? v : 0.2f * v; }

// ---------------- weight packing: Wp[k][0..M) = W, plus es/ed combined columns ----------------
// es[n,h] = sum_o h[n,h*O+o]*as[h,o]  ==>  es = x @ (W . as) : fold attention dot into GEMM.
__global__ void pack_weights(const float* __restrict__ W, const float* __restrict__ avs,
                             const float* __restrict__ avd, int which,
                             int K, int M, int MP, int KP, int H, int O, int ES, int ED) {
    float* Wp = (which == 0) ? g_Wp0 : (which == 1) ? g_Wp1 : g_Wp2;
    int i = blockIdx.x * blockDim.x + threadIdx.x;
    if (i >= KP * MP) return;
    int k = i / MP, j = i % MP;
    float v = 0.f;
    if (k < K) {
        if (j < M) {
            v = W[k * M + j];
        } else if (j >= ES && j < ES + H) {
            int h = j - ES; float s = 0.f;
            for (int o = 0; o < O; o++) s += W[k * M + h * O + o] * avs[h * O + o];
            v = s;
        } else if (j >= ED && j < ED + H) {
            int h = j - ED; float s = 0.f;
            for (int o = 0; o < O; o++) s += W[k * M + h * O + o] * avd[h * O + o];
            v = s;
        }
    }
    Wp[i] = v;
}

// ---------------- CSR build ----------------
__global__ void zero_aux() {
    int i = blockIdx.x * blockDim.x + threadIdx.x;
    if (i < NNODES) { g_deg[i] = 0; g_cur[i] = 0; }
    if (i < NGRAPHS * 128) g_pool[i] = 0.f;
    if (i < NGRAPHS) g_cnt[i] = 0;
}

__global__ void hist_kernel(const int* __restrict__ dstv) {
    int i = blockIdx.x * blockDim.x + threadIdx.x;
    if (i < NEDGES) atomicAdd(&g_deg[dstv[i]], 1);
}

__global__ void scan_kernel() {
    __shared__ int buf[1024];
    int t = threadIdx.x;
    int run = 0;
    if (t == 0) g_rowptr[0] = 0;
    for (int base = 0; base < NNODES; base += 1024) {
        int idx = base + t;
        int v = (idx < NNODES) ? g_deg[idx] : 0;
        buf[t] = v;
        __syncthreads();
        for (int off = 1; off < 1024; off <<= 1) {
            int a = (t >= off) ? buf[t - off] : 0;
            __syncthreads();
            buf[t] += a;
            __syncthreads();
        }
        int incl = buf[t];
        int tot = buf[1023];
        if (idx < NNODES) g_rowptr[idx + 1] = run + incl;
        run += tot;
        __syncthreads();
    }
}

__global__ void fill_kernel(const int* __restrict__ srcv, const int* __restrict__ dstv) {
    int i = blockIdx.x * blockDim.x + threadIdx.x;
    if (i < NEDGES) {
        int d = dstv[i];
        int p = atomicAdd(&g_cur[d], 1);
        g_col[g_rowptr[d] + p] = srcv[i];
    }
}

// ---------------- layer-0 GEMM (K=6), writes g_h stride 144 incl. es/ed ----------------
__global__ void gemm0_kernel(const float* __restrict__ x) {
    int n = blockIdx.x;
    int j = threadIdx.x;
    float xr[6];
#pragma unroll
    for (int k = 0; k < 6; k++) xr[k] = __ldg(&x[n * 6 + k]);
    if (j < 144) {
        float a = 0.f;
#pragma unroll
        for (int k = 0; k < 6; k++) a += xr[k] * g_Wp0[k * 144 + j];
        g_h[(size_t)n * 144 + j] = a;
    }
}

// ---------------- tiled GEMM: g_act[N,132] @ Wp[132,MP] -> g_h[N,MP] ----------------
// 64 nodes/block, thread = (MP/4 cols) x (8 node-groups), 8 nodes x 4 cols per thread.
template <int MP>
__global__ void gemm_tiled(int wsel, int N) {
    constexpr int KP = 132;
    constexpr int TXN = MP / 4;
    constexpr int NTH = TXN * 8;
    __shared__ float xs[KP][68];  // transposed A tile, row stride 68 floats (272B, 16B-aligned)
    const float* Wp = (wsel == 1) ? g_Wp1 : g_Wp2;
    const float4* W4 = (const float4*)Wp;
    int tx = threadIdx.x, ty = threadIdx.y;
    int t = ty * TXN + tx;
    int n0 = blockIdx.x * 64;
    // stage A tile (transposed)
    for (int i = t; i < 64 * 33; i += NTH) {
        int n = i / 33, k4 = i % 33;
        int gn = n0 + n;
        float4 v = make_float4(0.f, 0.f, 0.f, 0.f);
        if (gn < N) v = __ldg((const float4*)(g_act + (size_t)gn * 132 + k4 * 4));
        xs[k4 * 4 + 0][n] = v.x;
        xs[k4 * 4 + 1][n] = v.y;
        xs[k4 * 4 + 2][n] = v.z;
        xs[k4 * 4 + 3][n] = v.w;
    }
    __syncthreads();
    float acc[8][4];
#pragma unroll
    for (int r = 0; r < 8; r++)
#pragma unroll
        for (int c = 0; c < 4; c++) acc[r][c] = 0.f;
    int nb = ty * 8;
#pragma unroll 4
    for (int k = 0; k < KP; k++) {
        float4 w = __ldg(&W4[k * TXN + tx]);
        float4 xa = *(const float4*)&xs[k][nb];
        float4 xb = *(const float4*)&xs[k][nb + 4];
        float xv[8] = {xa.x, xa.y, xa.z, xa.w, xb.x, xb.y, xb.z, xb.w};
#pragma unroll
        for (int r = 0; r < 8; r++) {
            acc[r][0] += xv[r] * w.x;
            acc[r][1] += xv[r] * w.y;
            acc[r][2] += xv[r] * w.z;
            acc[r][3] += xv[r] * w.w;
        }
    }
#pragma unroll
    for (int r = 0; r < 8; r++) {
        int gn = n0 + nb + r;
        if (gn < N) {
            float4 o = make_float4(acc[r][0], acc[r][1], acc[r][2], acc[r][3]);
            *(float4*)(g_h + (size_t)gn * MP + tx * 4) = o;
        }
    }
}

// ---------------- GAT gather: warp per dst node, CSR in-edges + implicit self-loop ----------------
// pass1: segment max of leaky(es[src]+ed[dst]); pass2: exp-weighted sum of h[src]; normalize+bias+act.
template <int H, int O, int M, int SIN, int ESOFF, int EDOFF, int SOUT, int ACT>
__global__ void gather_kernel(const float* __restrict__ bias) {
    int gw = (blockIdx.x * blockDim.x + threadIdx.x) >> 5;
    int lane = threadIdx.x & 31;
    if (gw >= NNODES) return;
    int n = gw;
    const float* hn = g_h + (size_t)n * SIN;
    float edv[3], esn[3], selfe[3], mx[3];
#pragma unroll
    for (int h = 0; h < H; h++) {
        edv[h] = __ldg(&hn[EDOFF + h]);
        esn[h] = __ldg(&hn[ESOFF + h]);
        selfe[h] = leakyf(esn[h] + edv[h]);
        mx[h] = selfe[h];
    }
    int beg = __ldg(&g_rowptr[n]);
    int end = __ldg(&g_rowptr[n + 1]);
    // pass 1: max over in-edges (lanes parallel over edges)
    for (int e = beg + lane; e < end; e += 32) {
        int s = __ldg(&g_col[e]);
        float4 eq = __ldg((const float4*)(g_h + (size_t)s * SIN + ESOFF));
        mx[0] = fmaxf(mx[0], leakyf(eq.x + edv[0]));
        if (H > 1) mx[1] = fmaxf(mx[1], leakyf(eq.y + edv[1]));
        if (H > 2) mx[2] = fmaxf(mx[2], leakyf(eq.z + edv[2]));
    }
#pragma unroll
    for (int h = 0; h < H; h++)
#pragma unroll
        for (int o = 16; o > 0; o >>= 1) mx[h] = fmaxf(mx[h], __shfl_xor_sync(0xffffffffu, mx[h], o));
    // pass 2: accumulate (edges sequential, lanes over features)
    constexpr int NI = (M + 31) / 32;
    float z[3] = {0.f, 0.f, 0.f};
    float w0s, w1s = 0.f, w2s = 0.f;
    w0s = __expf(selfe[0] - mx[0]); z[0] = w0s;
    if (H > 1) { w1s = __expf(selfe[1] - mx[1]); z[1] = w1s; }
    if (H > 2) { w2s = __expf(selfe[2] - mx[2]); z[2] = w2s; }
    float acc[NI];
#pragma unroll
    for (int i = 0; i < NI; i++) {
        int j = lane + 32 * i;
        if (j < M) {
            int hdi = j / O;
            float ws = (H == 1) ? w0s : (hdi == 0 ? w0s : (hdi == 1 ? w1s : w2s));
            acc[i] = ws * __ldg(&hn[j]);
        } else acc[i] = 0.f;
    }
    int e = beg;
    int s_next = (e < end) ? __ldg(&g_col[e]) : 0;
    while (e < end) {
        int s = s_next;
        if (e + 1 < end) s_next = __ldg(&g_col[e + 1]);
        const float* hs = g_h + (size_t)s * SIN;
        float4 eq = __ldg((const float4*)(hs + ESOFF));
        float w0 = __expf(leakyf(eq.x + edv[0]) - mx[0]); z[0] += w0;
        float w1 = w0, w2 = w0;
        if (H > 1) { w1 = __expf(leakyf(eq.y + edv[1]) - mx[1]); z[1] += w1; }
        if (H > 2) { w2 = __expf(leakyf(eq.z + edv[2]) - mx[2]); z[2] += w2; }
#pragma unroll
        for (int i = 0; i < NI; i++) {
            int j = lane + 32 * i;
            if (j < M) {
                int hdi = j / O;
                float ws = (H == 1) ? w0 : (hdi == 0 ? w0 : (hdi == 1 ? w1 : w2));
                acc[i] += ws * __ldg(&hs[j]);
            }
        }
        e++;
    }
#pragma unroll
    for (int i = 0; i < NI; i++) {
        int j = lane + 32 * i;
        if (j < M) {
            int hdi = j / O;
            float zz = (H == 1) ? z[0] : (hdi == 0 ? z[0] : (hdi == 1 ? z[1] : z[2]));
            float v = acc[i] / (zz + 1e-16f) + __ldg(&bias[j]);
            if (ACT) v = leakyf(v);
            g_act[(size_t)n * SOUT + j] = v;
        }
    }
}

// ---------------- global mean pool over graphs (vector atomics, sm_90+) ----------------
__global__ void pool_kernel(const int* __restrict__ batch) {
    int gw = (blockIdx.x * blockDim.x + threadIdx.x) >> 5;
    int lane = threadIdx.x & 31;
    if (gw >= NNODES) return;
    int b = __ldg(&batch[gw]);
    float4 v = __ldg((const float4*)(g_act + (size_t)gw * 128) + lane);
    atomicAdd(reinterpret_cast<float4*>(g_pool + b * 128) + lane, v);
    if (lane == 0) atomicAdd(&g_cnt[b], 1);
}

__global__ void finalize_kernel(float* __restrict__ out) {
    int b = blockIdx.x, j = threadIdx.x;
    int c = g_cnt[b];
    float cf = (float)(c > 1 ? c : 1);
    out[b * 256 + j] = g_pool[b * 128 + j] / cf;
}

// ---------------- location encoder MLP + mean over locations ----------------
__global__ void locmlp_kernel(const float* __restrict__ loc, const float* __restrict__ Wl1,
                              const float* __restrict__ bl1, const float* __restrict__ Wl2,
                              const float* __restrict__ bl2, float* __restrict__ out) {
    int b = blockIdx.x;
    int t = threadIdx.x;  // 256
    __shared__ float hid[256];
    float accv = 0.f;
    for (int l = 0; l < NLOCS; l++) {
        float lx = __ldg(&loc[(b * NLOCS + l) * 2 + 0]);
        float ly = __ldg(&loc[(b * NLOCS + l) * 2 + 1]);
        float hv = tanhf(lx * __ldg(&Wl1[t]) + ly * __ldg(&Wl1[256 + t]) + __ldg(&bl1[t]));
        __syncthreads();
        hid[t] = hv;
        __syncthreads();
        if (t < 128) {
            float s = 0.f;
#pragma unroll 8
            for (int k = 0; k < 256; k++) s += hid[k] * __ldg(&Wl2[k * 128 + t]);
            accv += s;
        }
    }
    if (t < 128) out[b * 256 + 128 + t] = accv / (float)NLOCS + __ldg(&bl2[t]);
}

// ---------------- launch ----------------
extern "C" void kernel_launch(void* const* d_in, const int* in_sizes, int n_in,
                              void* d_out, int out_size) {
    const float* x   = (const float*)d_in[0];
    const float* loc = (const float*)d_in[1];
    const int* ei    = (const int*)d_in[2];
    const int* batch = (const int*)d_in[3];
    const float* W0  = (const float*)d_in[4];
    const float* as0 = (const float*)d_in[5];
    const float* ad0 = (const float*)d_in[6];
    const float* b0  = (const float*)d_in[7];
    const float* W1  = (const float*)d_in[8];
    const float* as1 = (const float*)d_in[9];
    const float* ad1 = (const float*)d_in[10];
    const float* b1  = (const float*)d_in[11];
    const float* W2  = (const float*)d_in[12];
    const float* as2 = (const float*)d_in[13];
    const float* ad2 = (const float*)d_in[14];
    const float* b2  = (const float*)d_in[15];
    const float* Wl1 = (const float*)d_in[16];
    const float* bl1 = (const float*)d_in[17];
    const float* Wl2 = (const float*)d_in[18];
    const float* bl2 = (const float*)d_in[19];
    float* out = (float*)d_out;
    const int* srcv = ei;
    const int* dstv = ei + NEDGES;

    // pack weights (features + folded attention vectors)
    pack_weights<<<(8 * 144 + 255) / 256, 256>>>(W0, as0, ad0, 0, 6, 129, 144, 8, 3, 43, 132, 136);
    pack_weights<<<(132 * 144 + 255) / 256, 256>>>(W1, as1, ad1, 1, 129, 129, 144, 132, 3, 43, 132, 136);
    pack_weights<<<(132 * 132 + 255) / 256, 256>>>(W2, as2, ad2, 2, 129, 128, 132, 132, 1, 128, 128, 129);

    // CSR build by dst
    zero_aux<<<(NNODES + 255) / 256, 256>>>();
    hist_kernel<<<(NEDGES + 255) / 256, 256>>>(dstv);
    scan_kernel<<<1, 1024>>>();
    fill_kernel<<<(NEDGES + 255) / 256, 256>>>(srcv, dstv);

    int gatherBlocks = (NNODES + 7) / 8;  // 8 warps per 256-thread block
    int gemmBlocks = (NNODES + 63) / 64;

    // layer 0
    gemm0_kernel<<<NNODES, 160>>>(x);
    gather_kernel<3, 43, 129, 144, 132, 136, 132, 1><<<gatherBlocks, 256>>>(b0);
    // layer 1
    gemm_tiled<144><<<gemmBlocks, dim3(36, 8)>>>(1, NNODES);
    gather_kernel<3, 43, 129, 144, 132, 136, 132, 1><<<gatherBlocks, 256>>>(b1);
    // layer 2 (heads=1, no activation)
    gemm_tiled<132><<<gemmBlocks, dim3(33, 8)>>>(2, NNODES);
    gather_kernel<1, 128, 128, 132, 128, 129, 128, 0><<<gatherBlocks, 256>>>(b2);

    // pooling + outputs
    pool_kernel<<<gatherBlocks, 256>>>(batch);
    finalize_kernel<<<64, 128>>>(out);
    locmlp_kernel<<<64, 256>>>(loc, Wl1, bl1, Wl2, bl2, out);
}